// round 2
// baseline (speedup 1.0000x reference)
#include <cuda_runtime.h>

#define BB   8
#define NPTS 8192
#define SPTS 2048
#define D1C  128
#define D2C  256
#define INCH 384
#define C1   256
#define C2   128

// ---------------- scratch (device globals; no allocation allowed) ----------
__device__ int   g_idx[BB * NPTS * 3];
__device__ float g_w[BB * NPTS * 3];
__device__ float g_WbT[D2C * C1];                    // [d][o]
__device__ float g_Zt[BB * SPTS * C1];               // [b][s][o]  o contiguous
__device__ float g_Y1[BB * C1 * NPTS];               // [b][o][n]
__device__ float g_Y2[BB * C2 * NPTS];               // [b][o][n]
__device__ float g_sum1[C1], g_sq1[C1], g_a0[C1], g_c0[C1];
__device__ float g_sum2[C2], g_sq2[C2], g_a1[C2], g_c1[C2];

// ---------------- 1) 3-NN + interpolation weights --------------------------
__global__ void knn_kernel(const float* __restrict__ xyz1,
                           const float* __restrict__ xyz2) {
    __shared__ float4 s2[SPTS];                       // 32 KB
    const int b = blockIdx.y;
    const int tid = threadIdx.x;
    for (int s = tid; s < SPTS; s += 256) {
        float x = xyz2[(b * 3 + 0) * SPTS + s];
        float y = xyz2[(b * 3 + 1) * SPTS + s];
        float z = xyz2[(b * 3 + 2) * SPTS + s];
        s2[s] = make_float4(x, y, z, x * x + y * y + z * z);
    }
    __syncthreads();
    const int n = blockIdx.x * 256 + tid;
    const float px = xyz1[(b * 3 + 0) * NPTS + n];
    const float py = xyz1[(b * 3 + 1) * NPTS + n];
    const float pz = xyz1[(b * 3 + 2) * NPTS + n];
    const float n1 = px * px + py * py + pz * pz;
    float d0 = 3.4e38f, d1 = 3.4e38f, d2 = 3.4e38f;
    int   i0 = 0, i1 = 0, i2 = 0;
#pragma unroll 4
    for (int s = 0; s < SPTS; s++) {
        float4 q = s2[s];
        float d = n1 + q.w - 2.f * (px * q.x + py * q.y + pz * q.z);
        if (d < d2) {
            if (d < d1) {
                d2 = d1; i2 = i1;
                if (d < d0) { d1 = d0; i1 = i0; d0 = d; i0 = s; }
                else        { d1 = d;  i1 = s; }
            } else { d2 = d; i2 = s; }
        }
    }
    const float r0 = 1.f / (d0 + 1e-8f);
    const float r1 = 1.f / (d1 + 1e-8f);
    const float r2 = 1.f / (d2 + 1e-8f);
    const float inv = 1.f / (r0 + r1 + r2);
    const int base = (b * NPTS + n) * 3;
    g_idx[base + 0] = i0; g_idx[base + 1] = i1; g_idx[base + 2] = i2;
    g_w[base + 0] = r0 * inv; g_w[base + 1] = r1 * inv; g_w[base + 2] = r2 * inv;
}

// ---------------- 2) transpose W0's D2-half: WbT[d][o] = W0[o][128+d] ------
__global__ void transpose_w0b(const float* __restrict__ W0) {
    const int d = blockIdx.x, o = threadIdx.x;
    g_WbT[d * C1 + o] = W0[o * INCH + D1C + d];
}

// ---------------- 3) Zt[b][s][o] = sum_d points2[b][d][s] * WbT[d][o] ------
// block tile 128(s) x 128(o), K-tile 16, 256 threads, 8x8 micro
__global__ void __launch_bounds__(256, 2) gemm_zt(const float* __restrict__ points2) {
    const int b    = blockIdx.z;
    const int sblk = blockIdx.x * 128;
    const int oblk = blockIdx.y * 128;
    __shared__ __align__(16) float As[16][128];       // [k][s]
    __shared__ __align__(16) float Bs[16][128];       // [k][o]
    const int tid = threadIdx.x;
    const int ts = tid % 16, to = tid / 16;           // micro coords
    const int ldr = tid / 16, ldc = (tid % 16) * 8;   // staging coords
    const float* P2 = points2 + b * D2C * SPTS;
    float acc[8][8] = {};
    for (int kt = 0; kt < D2C; kt += 16) {
        const float* asrc = P2 + (kt + ldr) * SPTS + sblk + ldc;
        *(float4*)&As[ldr][ldc]     = *(const float4*)asrc;
        *(float4*)&As[ldr][ldc + 4] = *(const float4*)(asrc + 4);
        const float* bsrc = g_WbT + (kt + ldr) * C1 + oblk + ldc;
        *(float4*)&Bs[ldr][ldc]     = *(const float4*)bsrc;
        *(float4*)&Bs[ldr][ldc + 4] = *(const float4*)(bsrc + 4);
        __syncthreads();
#pragma unroll
        for (int k = 0; k < 16; k++) {
            float a[8], bv[8];
            *(float4*)(a)      = *(const float4*)&As[k][ts * 8];
            *(float4*)(a + 4)  = *(const float4*)&As[k][ts * 8 + 4];
            *(float4*)(bv)     = *(const float4*)&Bs[k][to * 8];
            *(float4*)(bv + 4) = *(const float4*)&Bs[k][to * 8 + 4];
#pragma unroll
            for (int i = 0; i < 8; i++)
#pragma unroll
                for (int j = 0; j < 8; j++)
                    acc[i][j] = fmaf(a[i], bv[j], acc[i][j]);
        }
        __syncthreads();
    }
    float* Z = g_Zt + (b * SPTS + sblk + ts * 8) * C1 + oblk + to * 8;
#pragma unroll
    for (int i = 0; i < 8; i++) {
        *(float4*)(Z + i * C1)     = make_float4(acc[i][0], acc[i][1], acc[i][2], acc[i][3]);
        *(float4*)(Z + i * C1 + 4) = make_float4(acc[i][4], acc[i][5], acc[i][6], acc[i][7]);
    }
}

// ---------------- 4) Y1 = W0a @ p1 + gather(Zt, idx, w) + b0 ---------------
// block: full 256(o) x 64(n), K=128 in tiles of 16, 256 threads, 8x8 micro
__global__ void __launch_bounds__(256, 2) gemm_y1(const float* __restrict__ W0,
                                                  const float* __restrict__ points1,
                                                  const float* __restrict__ b0) {
    const int b    = blockIdx.y;
    const int nblk = blockIdx.x * 64;
    __shared__ __align__(16) float As[16][C1];        // [k][o]  16 KB
    __shared__ __align__(16) float Bs[16][64];        // [k][n]  4 KB
    __shared__ int   sIdx[64][3];
    __shared__ float sW[64][3];
    const int tid = threadIdx.x;
    if (tid < 192) {
        const int nl = tid / 3, j = tid % 3;
        const int base = (b * NPTS + nblk + nl) * 3 + j;
        sIdx[nl][j] = g_idx[base];
        sW[nl][j]   = g_w[base];
    }
    const int tn = tid % 8, to = tid / 8;             // nbase=tn*8, obase=to*8
    const float* P1 = points1 + b * D1C * NPTS;
    float acc[8][8] = {};                             // [o][n]
    for (int kt = 0; kt < D1C; kt += 16) {
        {   // As: o = tid, 16 k-values from W0 row (transpose into shared)
            const float* w = W0 + tid * INCH + kt;
            float4 v0 = *(const float4*)w;
            float4 v1 = *(const float4*)(w + 4);
            float4 v2 = *(const float4*)(w + 8);
            float4 v3 = *(const float4*)(w + 12);
            As[0][tid] = v0.x;  As[1][tid] = v0.y;  As[2][tid] = v0.z;  As[3][tid] = v0.w;
            As[4][tid] = v1.x;  As[5][tid] = v1.y;  As[6][tid] = v1.z;  As[7][tid] = v1.w;
            As[8][tid] = v2.x;  As[9][tid] = v2.y;  As[10][tid] = v2.z; As[11][tid] = v2.w;
            As[12][tid] = v3.x; As[13][tid] = v3.y; As[14][tid] = v3.z; As[15][tid] = v3.w;
        }
        {   // Bs
            const int r = tid / 16, c = (tid % 16) * 4;
            *(float4*)&Bs[r][c] = *(const float4*)(P1 + (kt + r) * NPTS + nblk + c);
        }
        __syncthreads();
#pragma unroll
        for (int k = 0; k < 16; k++) {
            float a[8], bv[8];
            *(float4*)(a)      = *(const float4*)&As[k][to * 8];
            *(float4*)(a + 4)  = *(const float4*)&As[k][to * 8 + 4];
            *(float4*)(bv)     = *(const float4*)&Bs[k][tn * 8];
            *(float4*)(bv + 4) = *(const float4*)&Bs[k][tn * 8 + 4];
#pragma unroll
            for (int i = 0; i < 8; i++)
#pragma unroll
                for (int j = 0; j < 8; j++)
                    acc[i][j] = fmaf(a[i], bv[j], acc[i][j]);
        }
        __syncthreads();
    }
    // gather epilogue: coalesced rows of Zt (o contiguous), L2-resident
#pragma unroll
    for (int j = 0; j < 8; j++) {
        const int nl = tn * 8 + j;
#pragma unroll
        for (int t = 0; t < 3; t++) {
            const int   s = sIdx[nl][t];
            const float w = sW[nl][t];
            const float* zr = g_Zt + (b * SPTS + s) * C1 + to * 8;
            float4 z0 = *(const float4*)zr;
            float4 z1 = *(const float4*)(zr + 4);
            acc[0][j] = fmaf(w, z0.x, acc[0][j]);
            acc[1][j] = fmaf(w, z0.y, acc[1][j]);
            acc[2][j] = fmaf(w, z0.z, acc[2][j]);
            acc[3][j] = fmaf(w, z0.w, acc[3][j]);
            acc[4][j] = fmaf(w, z1.x, acc[4][j]);
            acc[5][j] = fmaf(w, z1.y, acc[5][j]);
            acc[6][j] = fmaf(w, z1.z, acc[6][j]);
            acc[7][j] = fmaf(w, z1.w, acc[7][j]);
        }
    }
    float bias[8];
#pragma unroll
    for (int i = 0; i < 8; i++) bias[i] = b0[to * 8 + i];
    float* Y = g_Y1 + (b * C1 + to * 8) * NPTS + nblk + tn * 8;
#pragma unroll
    for (int i = 0; i < 8; i++) {
        *(float4*)(Y + i * NPTS) =
            make_float4(acc[i][0] + bias[i], acc[i][1] + bias[i],
                        acc[i][2] + bias[i], acc[i][3] + bias[i]);
        *(float4*)(Y + i * NPTS + 4) =
            make_float4(acc[i][4] + bias[i], acc[i][5] + bias[i],
                        acc[i][6] + bias[i], acc[i][7] + bias[i]);
    }
}

// ---------------- 5) BN1 stats -------------------------------------------
__global__ void reduce1() {
    const int c = blockIdx.x;
    float s = 0.f, q = 0.f;
    for (int b = 0; b < BB; b++) {
        const float* p = g_Y1 + (b * C1 + c) * NPTS;
        for (int n = threadIdx.x * 4; n < NPTS; n += 1024) {
            float4 v = *(const float4*)(p + n);
            s += (v.x + v.y) + (v.z + v.w);
            q += (v.x * v.x + v.y * v.y) + (v.z * v.z + v.w * v.w);
        }
    }
    __shared__ float ss[256], sq[256];
    ss[threadIdx.x] = s; sq[threadIdx.x] = q;
    __syncthreads();
    for (int st = 128; st > 0; st >>= 1) {
        if (threadIdx.x < st) {
            ss[threadIdx.x] += ss[threadIdx.x + st];
            sq[threadIdx.x] += sq[threadIdx.x + st];
        }
        __syncthreads();
    }
    if (threadIdx.x == 0) { g_sum1[c] = ss[0]; g_sq1[c] = sq[0]; }
}

__global__ void finalize1(const float* __restrict__ g0, const float* __restrict__ be0) {
    const int c = threadIdx.x;
    const float cnt = (float)(BB * NPTS);
    const float mean = g_sum1[c] / cnt;
    const float var  = g_sq1[c] / cnt - mean * mean;
    const float a = g0[c] * rsqrtf(var + 1e-5f);
    g_a0[c] = a;
    g_c0[c] = be0[c] - mean * a;
}

// ---------------- 6) Y2 = W1 @ relu(a0*Y1 + c0) + b1 -----------------------
// block: 128(o) x 128(n), K=256 in tiles of 16, 256 threads, 8x8 micro
__global__ void __launch_bounds__(256, 2) gemm_y2(const float* __restrict__ W1,
                                                  const float* __restrict__ b1) {
    const int b    = blockIdx.y;
    const int nblk = blockIdx.x * 128;
    __shared__ __align__(16) float As[16][C2];        // [k][o]
    __shared__ __align__(16) float Bs[16][128];       // [k][n]
    const int tid = threadIdx.x;
    const int tn = tid % 16, to = tid / 16;           // nbase=tn*8, obase=to*8
    float acc[8][8] = {};
    for (int kt = 0; kt < C1; kt += 16) {
        {   // As: o = tid/2, 8 k-values
            const int o = tid >> 1, kk = (tid & 1) * 8;
            const float* w = W1 + o * C1 + kt + kk;
            float4 v0 = *(const float4*)w;
            float4 v1 = *(const float4*)(w + 4);
            As[kk + 0][o] = v0.x; As[kk + 1][o] = v0.y;
            As[kk + 2][o] = v0.z; As[kk + 3][o] = v0.w;
            As[kk + 4][o] = v1.x; As[kk + 5][o] = v1.y;
            As[kk + 6][o] = v1.z; As[kk + 7][o] = v1.w;
        }
        {   // Bs: apply BN1 + relu while staging
            const int r = tid / 16, c = (tid % 16) * 8;
            const int ch = kt + r;
            const float am = g_a0[ch], cm = g_c0[ch];
            const float* y = g_Y1 + (b * C1 + ch) * NPTS + nblk + c;
            float4 v0 = *(const float4*)y;
            float4 v1 = *(const float4*)(y + 4);
            Bs[r][c + 0] = fmaxf(fmaf(am, v0.x, cm), 0.f);
            Bs[r][c + 1] = fmaxf(fmaf(am, v0.y, cm), 0.f);
            Bs[r][c + 2] = fmaxf(fmaf(am, v0.z, cm), 0.f);
            Bs[r][c + 3] = fmaxf(fmaf(am, v0.w, cm), 0.f);
            Bs[r][c + 4] = fmaxf(fmaf(am, v1.x, cm), 0.f);
            Bs[r][c + 5] = fmaxf(fmaf(am, v1.y, cm), 0.f);
            Bs[r][c + 6] = fmaxf(fmaf(am, v1.z, cm), 0.f);
            Bs[r][c + 7] = fmaxf(fmaf(am, v1.w, cm), 0.f);
        }
        __syncthreads();
#pragma unroll
        for (int k = 0; k < 16; k++) {
            float a[8], bv[8];
            *(float4*)(a)      = *(const float4*)&As[k][to * 8];
            *(float4*)(a + 4)  = *(const float4*)&As[k][to * 8 + 4];
            *(float4*)(bv)     = *(const float4*)&Bs[k][tn * 8];
            *(float4*)(bv + 4) = *(const float4*)&Bs[k][tn * 8 + 4];
#pragma unroll
            for (int i = 0; i < 8; i++)
#pragma unroll
                for (int j = 0; j < 8; j++)
                    acc[i][j] = fmaf(a[i], bv[j], acc[i][j]);
        }
        __syncthreads();
    }
    float bias[8];
#pragma unroll
    for (int i = 0; i < 8; i++) bias[i] = b1[to * 8 + i];
    float* Y = g_Y2 + (b * C2 + to * 8) * NPTS + nblk + tn * 8;
#pragma unroll
    for (int i = 0; i < 8; i++) {
        *(float4*)(Y + i * NPTS) =
            make_float4(acc[i][0] + bias[i], acc[i][1] + bias[i],
                        acc[i][2] + bias[i], acc[i][3] + bias[i]);
        *(float4*)(Y + i * NPTS + 4) =
            make_float4(acc[i][4] + bias[i], acc[i][5] + bias[i],
                        acc[i][6] + bias[i], acc[i][7] + bias[i]);
    }
}

// ---------------- 7) BN2 stats + final epilogue ----------------------------
__global__ void reduce2() {
    const int c = blockIdx.x;
    float s = 0.f, q = 0.f;
    for (int b = 0; b < BB; b++) {
        const float* p = g_Y2 + (b * C2 + c) * NPTS;
        for (int n = threadIdx.x * 4; n < NPTS; n += 1024) {
            float4 v = *(const float4*)(p + n);
            s += (v.x + v.y) + (v.z + v.w);
            q += (v.x * v.x + v.y * v.y) + (v.z * v.z + v.w * v.w);
        }
    }
    __shared__ float ss[256], sq[256];
    ss[threadIdx.x] = s; sq[threadIdx.x] = q;
    __syncthreads();
    for (int st = 128; st > 0; st >>= 1) {
        if (threadIdx.x < st) {
            ss[threadIdx.x] += ss[threadIdx.x + st];
            sq[threadIdx.x] += sq[threadIdx.x + st];
        }
        __syncthreads();
    }
    if (threadIdx.x == 0) { g_sum2[c] = ss[0]; g_sq2[c] = sq[0]; }
}

__global__ void finalize2(const float* __restrict__ g1, const float* __restrict__ be1) {
    const int c = threadIdx.x;
    const float cnt = (float)(BB * NPTS);
    const float mean = g_sum2[c] / cnt;
    const float var  = g_sq2[c] / cnt - mean * mean;
    const float a = g1[c] * rsqrtf(var + 1e-5f);
    g_a1[c] = a;
    g_c1[c] = be1[c] - mean * a;
}

__global__ void apply2(float* __restrict__ out) {
    const int i = blockIdx.x * 256 + threadIdx.x;       // float4 index
    const int c = (i / (NPTS / 4)) % C2;
    const float a = g_a1[c], cc = g_c1[c];
    float4 v = ((const float4*)g_Y2)[i];
    v.x = fmaxf(fmaf(a, v.x, cc), 0.f);
    v.y = fmaxf(fmaf(a, v.y, cc), 0.f);
    v.z = fmaxf(fmaf(a, v.z, cc), 0.f);
    v.w = fmaxf(fmaf(a, v.w, cc), 0.f);
    ((float4*)out)[i] = v;
}

// ---------------------------------------------------------------------------
extern "C" void kernel_launch(void* const* d_in, const int* in_sizes, int n_in,
                              void* d_out, int out_size) {
    const float* xyz1    = (const float*)d_in[0];
    const float* xyz2    = (const float*)d_in[1];
    const float* points1 = (const float*)d_in[2];
    const float* points2 = (const float*)d_in[3];
    const float* W0      = (const float*)d_in[4];
    const float* b0      = (const float*)d_in[5];
    const float* g0      = (const float*)d_in[6];
    const float* be0     = (const float*)d_in[7];
    const float* W1      = (const float*)d_in[8];
    const float* b1      = (const float*)d_in[9];
    const float* g1      = (const float*)d_in[10];
    const float* be1     = (const float*)d_in[11];
    float* out = (float*)d_out;

    knn_kernel  <<<dim3(NPTS / 256, BB), 256>>>(xyz1, xyz2);
    transpose_w0b<<<D2C, C1>>>(W0);
    gemm_zt     <<<dim3(SPTS / 128, C1 / 128, BB), 256>>>(points2);
    gemm_y1     <<<dim3(NPTS / 64, BB), 256>>>(W0, points1, b0);
    reduce1     <<<C1, 256>>>();
    finalize1   <<<1, C1>>>(g0, be0);
    gemm_y2     <<<dim3(NPTS / 128, BB), 256>>>(W1, b1);
    reduce2     <<<C2, 256>>>();
    finalize2   <<<1, C2>>>(g1, be1);
    apply2      <<<(BB * C2 * NPTS / 4) / 256, 256>>>(out);
}

// round 3
// speedup vs baseline: 1.0670x; 1.0670x over previous
#include <cuda_runtime.h>

#define BB   8
#define NPTS 8192
#define SPTS 2048
#define D1C  128
#define D2C  256
#define INCH 384
#define C1   256
#define C2   128

typedef unsigned long long u64;

__device__ __forceinline__ u64 pk2(float lo, float hi) {
    u64 r;
    asm("mov.b64 %0, {%1, %2};" : "=l"(r)
        : "r"(__float_as_uint(lo)), "r"(__float_as_uint(hi)));
    return r;
}
__device__ __forceinline__ void upk2(u64 v, float& lo, float& hi) {
    unsigned a, b;
    asm("mov.b64 {%0, %1}, %2;" : "=r"(a), "=r"(b) : "l"(v));
    lo = __uint_as_float(a); hi = __uint_as_float(b);
}
__device__ __forceinline__ void ffma2(u64& d, u64 a, u64 b) {
    asm("fma.rn.f32x2 %0, %1, %2, %0;" : "+l"(d) : "l"(a), "l"(b));
}

// ---------------- scratch ---------------------------------------------------
__device__ int   g_idx[BB * NPTS * 3];
__device__ float g_w[BB * NPTS * 3];
__device__ float g_WbT[D2C * C1];                    // [d][o]
__device__ float g_Zt[BB * SPTS * C1];               // [b][s][o]  o contiguous
__device__ float g_Y1[BB * C1 * NPTS];               // [b][o][n]
__device__ float g_Y2[BB * C2 * NPTS];               // [b][o][n]
__device__ float g_p1s[C1 * 1024], g_p1q[C1 * 1024]; // per-block BN1 partials
__device__ float g_p2s[C2 * 512],  g_p2q[C2 * 512];  // per-block BN2 partials
__device__ float g_a0[C1], g_c0[C1];
__device__ float g_a1[C2], g_c1[C2];

// ---------------- 1) 3-NN + interpolation weights ---------------------------
__global__ void knn_kernel(const float* __restrict__ xyz1,
                           const float* __restrict__ xyz2) {
    __shared__ float4 s2[SPTS];                       // 32 KB
    const int b = blockIdx.y;
    const int tid = threadIdx.x;
    for (int s = tid; s < SPTS; s += 256) {
        float x = xyz2[(b * 3 + 0) * SPTS + s];
        float y = xyz2[(b * 3 + 1) * SPTS + s];
        float z = xyz2[(b * 3 + 2) * SPTS + s];
        s2[s] = make_float4(x, y, z, x * x + y * y + z * z);
    }
    __syncthreads();
    const int n = blockIdx.x * 256 + tid;
    const float px = xyz1[(b * 3 + 0) * NPTS + n];
    const float py = xyz1[(b * 3 + 1) * NPTS + n];
    const float pz = xyz1[(b * 3 + 2) * NPTS + n];
    const float n1 = px * px + py * py + pz * pz;
    float d0 = 3.4e38f, d1 = 3.4e38f, d2 = 3.4e38f;
    int   i0 = 0, i1 = 0, i2 = 0;
#pragma unroll 4
    for (int s = 0; s < SPTS; s++) {
        float4 q = s2[s];
        float d = n1 + q.w - 2.f * (px * q.x + py * q.y + pz * q.z);
        if (d < d2) {
            if (d < d1) {
                d2 = d1; i2 = i1;
                if (d < d0) { d1 = d0; i1 = i0; d0 = d; i0 = s; }
                else        { d1 = d;  i1 = s; }
            } else { d2 = d; i2 = s; }
        }
    }
    const float r0 = 1.f / (d0 + 1e-8f);
    const float r1 = 1.f / (d1 + 1e-8f);
    const float r2 = 1.f / (d2 + 1e-8f);
    const float inv = 1.f / (r0 + r1 + r2);
    const int base = (b * NPTS + n) * 3;
    g_idx[base + 0] = i0; g_idx[base + 1] = i1; g_idx[base + 2] = i2;
    g_w[base + 0] = r0 * inv; g_w[base + 1] = r1 * inv; g_w[base + 2] = r2 * inv;
}

// ---------------- 2) transpose W0's D2-half ---------------------------------
__global__ void transpose_w0b(const float* __restrict__ W0) {
    const int d = blockIdx.x, o = threadIdx.x;
    g_WbT[d * C1 + o] = W0[o * INCH + D1C + d];
}

// ---------------- 3) Zt[b][s][o] = sum_d points2[b][d][s] * WbT[d][o] -------
__global__ void __launch_bounds__(256, 2) gemm_zt(const float* __restrict__ points2) {
    const int b    = blockIdx.z;
    const int sblk = blockIdx.x * 128;
    const int oblk = blockIdx.y * 128;
    __shared__ __align__(16) float As[16][128];       // [k][s]
    __shared__ __align__(16) float Bs[16][128];       // [k][o]
    const int tid = threadIdx.x;
    const int ts = tid % 16, to = tid / 16;
    const int ldr = tid / 16, ldc = (tid % 16) * 8;
    const float* P2 = points2 + b * D2C * SPTS;
    u64 acc2[8][4] = {};
    for (int kt = 0; kt < D2C; kt += 16) {
        const float* asrc = P2 + (kt + ldr) * SPTS + sblk + ldc;
        *(float4*)&As[ldr][ldc]     = *(const float4*)asrc;
        *(float4*)&As[ldr][ldc + 4] = *(const float4*)(asrc + 4);
        const float* bsrc = g_WbT + (kt + ldr) * C1 + oblk + ldc;
        *(float4*)&Bs[ldr][ldc]     = *(const float4*)bsrc;
        *(float4*)&Bs[ldr][ldc + 4] = *(const float4*)(bsrc + 4);
        __syncthreads();
#pragma unroll
        for (int k = 0; k < 16; k++) {
            float4 a0 = *(const float4*)&As[k][ts * 8];
            float4 a1 = *(const float4*)&As[k][ts * 8 + 4];
            u64 da[8];
            da[0] = pk2(a0.x, a0.x); da[1] = pk2(a0.y, a0.y);
            da[2] = pk2(a0.z, a0.z); da[3] = pk2(a0.w, a0.w);
            da[4] = pk2(a1.x, a1.x); da[5] = pk2(a1.y, a1.y);
            da[6] = pk2(a1.z, a1.z); da[7] = pk2(a1.w, a1.w);
            ulonglong2 bq0 = *(const ulonglong2*)&Bs[k][to * 8];
            ulonglong2 bq1 = *(const ulonglong2*)&Bs[k][to * 8 + 4];
#pragma unroll
            for (int i = 0; i < 8; i++) {
                ffma2(acc2[i][0], da[i], bq0.x);
                ffma2(acc2[i][1], da[i], bq0.y);
                ffma2(acc2[i][2], da[i], bq1.x);
                ffma2(acc2[i][3], da[i], bq1.y);
            }
        }
        __syncthreads();
    }
    float* Z = g_Zt + (b * SPTS + sblk + ts * 8) * C1 + oblk + to * 8;
#pragma unroll
    for (int i = 0; i < 8; i++) {
        float v[8];
        upk2(acc2[i][0], v[0], v[1]); upk2(acc2[i][1], v[2], v[3]);
        upk2(acc2[i][2], v[4], v[5]); upk2(acc2[i][3], v[6], v[7]);
        *(float4*)(Z + i * C1)     = make_float4(v[0], v[1], v[2], v[3]);
        *(float4*)(Z + i * C1 + 4) = make_float4(v[4], v[5], v[6], v[7]);
    }
}

// ---------------- 4) Y1 = W0a @ p1 + gather(Zt) + b0 (+ BN1 partials) -------
__global__ void __launch_bounds__(256, 2) gemm_y1(const float* __restrict__ W0,
                                                  const float* __restrict__ points1,
                                                  const float* __restrict__ b0) {
    const int b    = blockIdx.y;
    const int nblk = blockIdx.x * 64;
    __shared__ __align__(16) float As[16][C1];        // [k][o]
    __shared__ __align__(16) float Bs[16][64];        // [k][n]
    __shared__ int   sIdx[64][3];
    __shared__ float sW[64][3];
    const int tid = threadIdx.x;
    if (tid < 192) {
        const int nl = tid / 3, j = tid % 3;
        const int base = (b * NPTS + nblk + nl) * 3 + j;
        sIdx[nl][j] = g_idx[base];
        sW[nl][j]   = g_w[base];
    }
    const int tn = tid % 8, to = tid / 8;
    const float* P1 = points1 + b * D1C * NPTS;
    __syncthreads();

    // --- gather of Zt first (scalar), then pack accumulators ---
    float acc[8][8] = {};
#pragma unroll
    for (int j = 0; j < 8; j++) {
        const int nl = tn * 8 + j;
#pragma unroll
        for (int t = 0; t < 3; t++) {
            const int   s = sIdx[nl][t];
            const float w = sW[nl][t];
            const float* zr = g_Zt + (b * SPTS + s) * C1 + to * 8;
            float4 z0 = *(const float4*)zr;
            float4 z1 = *(const float4*)(zr + 4);
            acc[0][j] = fmaf(w, z0.x, acc[0][j]);
            acc[1][j] = fmaf(w, z0.y, acc[1][j]);
            acc[2][j] = fmaf(w, z0.z, acc[2][j]);
            acc[3][j] = fmaf(w, z0.w, acc[3][j]);
            acc[4][j] = fmaf(w, z1.x, acc[4][j]);
            acc[5][j] = fmaf(w, z1.y, acc[5][j]);
            acc[6][j] = fmaf(w, z1.z, acc[6][j]);
            acc[7][j] = fmaf(w, z1.w, acc[7][j]);
        }
    }
    u64 acc2[8][4];
#pragma unroll
    for (int i = 0; i < 8; i++)
#pragma unroll
        for (int jp = 0; jp < 4; jp++)
            acc2[i][jp] = pk2(acc[i][2 * jp], acc[i][2 * jp + 1]);

    for (int kt = 0; kt < D1C; kt += 16) {
        {   // As: o = tid, 16 k-values from W0 row (transpose into shared)
            const float* w = W0 + tid * INCH + kt;
            float4 v0 = *(const float4*)w;
            float4 v1 = *(const float4*)(w + 4);
            float4 v2 = *(const float4*)(w + 8);
            float4 v3 = *(const float4*)(w + 12);
            As[0][tid] = v0.x;  As[1][tid] = v0.y;  As[2][tid] = v0.z;  As[3][tid] = v0.w;
            As[4][tid] = v1.x;  As[5][tid] = v1.y;  As[6][tid] = v1.z;  As[7][tid] = v1.w;
            As[8][tid] = v2.x;  As[9][tid] = v2.y;  As[10][tid] = v2.z; As[11][tid] = v2.w;
            As[12][tid] = v3.x; As[13][tid] = v3.y; As[14][tid] = v3.z; As[15][tid] = v3.w;
        }
        {   // Bs
            const int r = tid / 16, c = (tid % 16) * 4;
            *(float4*)&Bs[r][c] = *(const float4*)(P1 + (kt + r) * NPTS + nblk + c);
        }
        __syncthreads();
#pragma unroll
        for (int k = 0; k < 16; k++) {
            float4 a0 = *(const float4*)&As[k][to * 8];
            float4 a1 = *(const float4*)&As[k][to * 8 + 4];
            u64 da[8];
            da[0] = pk2(a0.x, a0.x); da[1] = pk2(a0.y, a0.y);
            da[2] = pk2(a0.z, a0.z); da[3] = pk2(a0.w, a0.w);
            da[4] = pk2(a1.x, a1.x); da[5] = pk2(a1.y, a1.y);
            da[6] = pk2(a1.z, a1.z); da[7] = pk2(a1.w, a1.w);
            ulonglong2 bq0 = *(const ulonglong2*)&Bs[k][tn * 8];
            ulonglong2 bq1 = *(const ulonglong2*)&Bs[k][tn * 8 + 4];
#pragma unroll
            for (int i = 0; i < 8; i++) {
                ffma2(acc2[i][0], da[i], bq0.x);
                ffma2(acc2[i][1], da[i], bq0.y);
                ffma2(acc2[i][2], da[i], bq1.x);
                ffma2(acc2[i][3], da[i], bq1.y);
            }
        }
        __syncthreads();
    }

    float* Y = g_Y1 + (b * C1 + to * 8) * NPTS + nblk + tn * 8;
#pragma unroll
    for (int i = 0; i < 8; i++) {
        const float bias = b0[to * 8 + i];
        float v[8];
        upk2(acc2[i][0], v[0], v[1]); upk2(acc2[i][1], v[2], v[3]);
        upk2(acc2[i][2], v[4], v[5]); upk2(acc2[i][3], v[6], v[7]);
        float s = 0.f, q = 0.f;
#pragma unroll
        for (int j = 0; j < 8; j++) { v[j] += bias; s += v[j]; q = fmaf(v[j], v[j], q); }
        *(float4*)(Y + i * NPTS)     = make_float4(v[0], v[1], v[2], v[3]);
        *(float4*)(Y + i * NPTS + 4) = make_float4(v[4], v[5], v[6], v[7]);
        // reduce over tn (8-lane groups), store per-block BN1 partials
#pragma unroll
        for (int off = 4; off > 0; off >>= 1) {
            s += __shfl_down_sync(0xffffffffu, s, off, 8);
            q += __shfl_down_sync(0xffffffffu, q, off, 8);
        }
        if (tn == 0) {
            const int slot = (to * 8 + i) * 1024 + b * 128 + blockIdx.x;
            g_p1s[slot] = s;
            g_p1q[slot] = q;
        }
    }
}

// ---------------- 5) BN1 stats from partials --------------------------------
__global__ void reduce1(const float* __restrict__ g0, const float* __restrict__ be0) {
    const int c = blockIdx.x;
    float s = 0.f, q = 0.f;
    for (int i = threadIdx.x; i < 1024; i += 256) {
        s += g_p1s[c * 1024 + i];
        q += g_p1q[c * 1024 + i];
    }
    __shared__ float ss[256], sq[256];
    ss[threadIdx.x] = s; sq[threadIdx.x] = q;
    __syncthreads();
    for (int st = 128; st > 0; st >>= 1) {
        if (threadIdx.x < st) {
            ss[threadIdx.x] += ss[threadIdx.x + st];
            sq[threadIdx.x] += sq[threadIdx.x + st];
        }
        __syncthreads();
    }
    if (threadIdx.x == 0) {
        const float cnt = (float)(BB * NPTS);
        const float mean = ss[0] / cnt;
        const float var  = sq[0] / cnt - mean * mean;
        const float a = g0[c] * rsqrtf(var + 1e-5f);
        g_a0[c] = a;
        g_c0[c] = be0[c] - mean * a;
    }
}

// ---------------- 6) Y2 = W1 @ relu(a0*Y1 + c0) + b1 (+ BN2 partials) -------
__global__ void __launch_bounds__(256, 2) gemm_y2(const float* __restrict__ W1,
                                                  const float* __restrict__ b1) {
    const int b    = blockIdx.y;
    const int nblk = blockIdx.x * 128;
    __shared__ __align__(16) float As[16][C2];        // [k][o]
    __shared__ __align__(16) float Bs[16][128];       // [k][n]
    const int tid = threadIdx.x;
    const int tn = tid % 16, to = tid / 16;
    u64 acc2[8][4] = {};
    for (int kt = 0; kt < C1; kt += 16) {
        {   // As
            const int o = tid >> 1, kk = (tid & 1) * 8;
            const float* w = W1 + o * C1 + kt + kk;
            float4 v0 = *(const float4*)w;
            float4 v1 = *(const float4*)(w + 4);
            As[kk + 0][o] = v0.x; As[kk + 1][o] = v0.y;
            As[kk + 2][o] = v0.z; As[kk + 3][o] = v0.w;
            As[kk + 4][o] = v1.x; As[kk + 5][o] = v1.y;
            As[kk + 6][o] = v1.z; As[kk + 7][o] = v1.w;
        }
        {   // Bs: BN1 + relu while staging
            const int r = tid / 16, c = (tid % 16) * 8;
            const int ch = kt + r;
            const float am = g_a0[ch], cm = g_c0[ch];
            const float* y = g_Y1 + (b * C1 + ch) * NPTS + nblk + c;
            float4 v0 = *(const float4*)y;
            float4 v1 = *(const float4*)(y + 4);
            Bs[r][c + 0] = fmaxf(fmaf(am, v0.x, cm), 0.f);
            Bs[r][c + 1] = fmaxf(fmaf(am, v0.y, cm), 0.f);
            Bs[r][c + 2] = fmaxf(fmaf(am, v0.z, cm), 0.f);
            Bs[r][c + 3] = fmaxf(fmaf(am, v0.w, cm), 0.f);
            Bs[r][c + 4] = fmaxf(fmaf(am, v1.x, cm), 0.f);
            Bs[r][c + 5] = fmaxf(fmaf(am, v1.y, cm), 0.f);
            Bs[r][c + 6] = fmaxf(fmaf(am, v1.z, cm), 0.f);
            Bs[r][c + 7] = fmaxf(fmaf(am, v1.w, cm), 0.f);
        }
        __syncthreads();
#pragma unroll
        for (int k = 0; k < 16; k++) {
            float4 a0 = *(const float4*)&As[k][to * 8];
            float4 a1 = *(const float4*)&As[k][to * 8 + 4];
            u64 da[8];
            da[0] = pk2(a0.x, a0.x); da[1] = pk2(a0.y, a0.y);
            da[2] = pk2(a0.z, a0.z); da[3] = pk2(a0.w, a0.w);
            da[4] = pk2(a1.x, a1.x); da[5] = pk2(a1.y, a1.y);
            da[6] = pk2(a1.z, a1.z); da[7] = pk2(a1.w, a1.w);
            ulonglong2 bq0 = *(const ulonglong2*)&Bs[k][tn * 8];
            ulonglong2 bq1 = *(const ulonglong2*)&Bs[k][tn * 8 + 4];
#pragma unroll
            for (int i = 0; i < 8; i++) {
                ffma2(acc2[i][0], da[i], bq0.x);
                ffma2(acc2[i][1], da[i], bq0.y);
                ffma2(acc2[i][2], da[i], bq1.x);
                ffma2(acc2[i][3], da[i], bq1.y);
            }
        }
        __syncthreads();
    }
    float* Y = g_Y2 + (b * C2 + to * 8) * NPTS + nblk + tn * 8;
#pragma unroll
    for (int i = 0; i < 8; i++) {
        const float bias = b1[to * 8 + i];
        float v[8];
        upk2(acc2[i][0], v[0], v[1]); upk2(acc2[i][1], v[2], v[3]);
        upk2(acc2[i][2], v[4], v[5]); upk2(acc2[i][3], v[6], v[7]);
        float s = 0.f, q = 0.f;
#pragma unroll
        for (int j = 0; j < 8; j++) { v[j] += bias; s += v[j]; q = fmaf(v[j], v[j], q); }
        *(float4*)(Y + i * NPTS)     = make_float4(v[0], v[1], v[2], v[3]);
        *(float4*)(Y + i * NPTS + 4) = make_float4(v[4], v[5], v[6], v[7]);
        // reduce over tn (16-lane groups), store per-block BN2 partials
#pragma unroll
        for (int off = 8; off > 0; off >>= 1) {
            s += __shfl_down_sync(0xffffffffu, s, off, 16);
            q += __shfl_down_sync(0xffffffffu, q, off, 16);
        }
        if (tn == 0) {
            const int slot = (to * 8 + i) * 512 + b * 64 + blockIdx.x;
            g_p2s[slot] = s;
            g_p2q[slot] = q;
        }
    }
}

// ---------------- 7) BN2 stats + final epilogue -----------------------------
__global__ void reduce2(const float* __restrict__ g1, const float* __restrict__ be1) {
    const int c = blockIdx.x;
    float s = 0.f, q = 0.f;
    for (int i = threadIdx.x; i < 512; i += 256) {
        s += g_p2s[c * 512 + i];
        q += g_p2q[c * 512 + i];
    }
    __shared__ float ss[256], sq[256];
    ss[threadIdx.x] = s; sq[threadIdx.x] = q;
    __syncthreads();
    for (int st = 128; st > 0; st >>= 1) {
        if (threadIdx.x < st) {
            ss[threadIdx.x] += ss[threadIdx.x + st];
            sq[threadIdx.x] += sq[threadIdx.x + st];
        }
        __syncthreads();
    }
    if (threadIdx.x == 0) {
        const float cnt = (float)(BB * NPTS);
        const float mean = ss[0] / cnt;
        const float var  = sq[0] / cnt - mean * mean;
        const float a = g1[c] * rsqrtf(var + 1e-5f);
        g_a1[c] = a;
        g_c1[c] = be1[c] - mean * a;
    }
}

__global__ void apply2(float* __restrict__ out) {
    const int i = blockIdx.x * 256 + threadIdx.x;       // float4 index
    const int c = (i / (NPTS / 4)) % C2;
    const float a = g_a1[c], cc = g_c1[c];
    float4 v = ((const float4*)g_Y2)[i];
    v.x = fmaxf(fmaf(a, v.x, cc), 0.f);
    v.y = fmaxf(fmaf(a, v.y, cc), 0.f);
    v.z = fmaxf(fmaf(a, v.z, cc), 0.f);
    v.w = fmaxf(fmaf(a, v.w, cc), 0.f);
    ((float4*)out)[i] = v;
}

// ---------------------------------------------------------------------------
extern "C" void kernel_launch(void* const* d_in, const int* in_sizes, int n_in,
                              void* d_out, int out_size) {
    const float* xyz1    = (const float*)d_in[0];
    const float* xyz2    = (const float*)d_in[1];
    const float* points1 = (const float*)d_in[2];
    const float* points2 = (const float*)d_in[3];
    const float* W0      = (const float*)d_in[4];
    const float* b0      = (const float*)d_in[5];
    const float* g0      = (const float*)d_in[6];
    const float* be0     = (const float*)d_in[7];
    const float* W1      = (const float*)d_in[8];
    const float* b1      = (const float*)d_in[9];
    const float* g1      = (const float*)d_in[10];
    const float* be1     = (const float*)d_in[11];
    float* out = (float*)d_out;

    knn_kernel  <<<dim3(NPTS / 256, BB), 256>>>(xyz1, xyz2);
    transpose_w0b<<<D2C, C1>>>(W0);
    gemm_zt     <<<dim3(SPTS / 128, C1 / 128, BB), 256>>>(points2);
    gemm_y1     <<<dim3(NPTS / 64, BB), 256>>>(W0, points1, b0);
    reduce1     <<<C1, 256>>>(g0, be0);
    gemm_y2     <<<dim3(NPTS / 128, BB), 256>>>(W1, b1);
    reduce2     <<<C2, 256>>>(g1, be1);
    apply2      <<<(BB * C2 * NPTS / 4) / 256, 256>>>(out);
}

// round 5
// speedup vs baseline: 1.4765x; 1.3838x over previous
#include <cuda_runtime.h>
#include <cuda_bf16.h>
#include <cstdint>

#define BB   8
#define NPTS 8192
#define SPTS 2048
#define D1C  128
#define D2C  256
#define INCH 384
#define C1   256
#define C2   128

// ===================== PTX helpers (standard sm_80+ ISA only) ===============
__device__ __forceinline__ uint32_t smem_u32(const void* p) {
    uint32_t a;
    asm("{ .reg .u64 t; cvta.to.shared.u64 t, %1; cvt.u32.u64 %0, t; }" : "=r"(a) : "l"(p));
    return a;
}
#define CP16(dst, src) \
    asm volatile("cp.async.cg.shared.global [%0], [%1], 16;" :: "r"(dst), "l"(src))
#define CP_COMMIT() asm volatile("cp.async.commit_group;" ::: "memory")
#define CP_WAIT0()  asm volatile("cp.async.wait_group 0;" ::: "memory")
#define CP_WAIT1()  asm volatile("cp.async.wait_group 1;" ::: "memory")

__device__ __forceinline__ void ldm4(uint32_t* r, uint32_t addr) {
    asm volatile("ldmatrix.sync.aligned.m8n8.x4.shared.b16 {%0,%1,%2,%3}, [%4];"
                 : "=r"(r[0]), "=r"(r[1]), "=r"(r[2]), "=r"(r[3]) : "r"(addr));
}
__device__ __forceinline__ void mma16816(float* c, const uint32_t* a, const uint32_t* b) {
    asm volatile("mma.sync.aligned.m16n8k16.row.col.f32.bf16.bf16.f32 "
                 "{%0,%1,%2,%3}, {%4,%5,%6,%7}, {%8,%9}, {%0,%1,%2,%3};"
                 : "+f"(c[0]), "+f"(c[1]), "+f"(c[2]), "+f"(c[3])
                 : "r"(a[0]), "r"(a[1]), "r"(a[2]), "r"(a[3]), "r"(b[0]), "r"(b[1]));
}

// ===================== scratch ==============================================
__device__ int   g_idx[BB * NPTS * 3];
__device__ float g_w[BB * NPTS * 3];

__device__ __nv_bfloat16 g_W0ah[C1 * D1C], g_W0al[C1 * D1C];
__device__ __nv_bfloat16 g_W0bh[C1 * D2C], g_W0bl[C1 * D2C];
__device__ __nv_bfloat16 g_W1h[C2 * C1],   g_W1l[C2 * C1];
__device__ __nv_bfloat16 g_P1h[BB * NPTS * D1C], g_P1l[BB * NPTS * D1C];
__device__ __nv_bfloat16 g_P2h[BB * SPTS * D2C], g_P2l[BB * SPTS * D2C];
__device__ __nv_bfloat16 g_A2h[BB * NPTS * C1],  g_A2l[BB * NPTS * C1];

__device__ float g_Zt[BB * SPTS * C1];     // [b][s][o]
__device__ float g_Y1[BB * NPTS * C1];     // [b][n][o]
__device__ float g_Y2[BB * NPTS * C2];     // [b][n][o]
__device__ float g_p1s[C1 * 64], g_p1q[C1 * 64];
__device__ float g_p2s[C2 * 64], g_p2q[C2 * 64];
__device__ float g_a0[C1], g_c0[C1], g_a1[C2], g_c1[C2];

// ===================== 1) 3-NN =============================================
__global__ void knn_kernel(const float* __restrict__ xyz1,
                           const float* __restrict__ xyz2) {
    __shared__ float4 s2[SPTS];
    const int b = blockIdx.y;
    const int tid = threadIdx.x;
    for (int s = tid; s < SPTS; s += 256) {
        float x = xyz2[(b * 3 + 0) * SPTS + s];
        float y = xyz2[(b * 3 + 1) * SPTS + s];
        float z = xyz2[(b * 3 + 2) * SPTS + s];
        s2[s] = make_float4(x, y, z, x * x + y * y + z * z);
    }
    __syncthreads();
    const int n = blockIdx.x * 256 + tid;
    const float px = xyz1[(b * 3 + 0) * NPTS + n];
    const float py = xyz1[(b * 3 + 1) * NPTS + n];
    const float pz = xyz1[(b * 3 + 2) * NPTS + n];
    const float n1 = px * px + py * py + pz * pz;
    float d0 = 3.4e38f, d1 = 3.4e38f, d2 = 3.4e38f;
    int   i0 = 0, i1 = 0, i2 = 0;
#pragma unroll 4
    for (int s = 0; s < SPTS; s++) {
        float4 q = s2[s];
        float d = n1 + q.w - 2.f * (px * q.x + py * q.y + pz * q.z);
        if (d < d2) {
            if (d < d1) {
                d2 = d1; i2 = i1;
                if (d < d0) { d1 = d0; i1 = i0; d0 = d; i0 = s; }
                else        { d1 = d;  i1 = s; }
            } else { d2 = d; i2 = s; }
        }
    }
    const float r0 = 1.f / (d0 + 1e-8f);
    const float r1 = 1.f / (d1 + 1e-8f);
    const float r2 = 1.f / (d2 + 1e-8f);
    const float inv = 1.f / (r0 + r1 + r2);
    const int base = (b * NPTS + n) * 3;
    g_idx[base + 0] = i0; g_idx[base + 1] = i1; g_idx[base + 2] = i2;
    g_w[base + 0] = r0 * inv; g_w[base + 1] = r1 * inv; g_w[base + 2] = r2 * inv;
}

// ===================== 2) weight split ======================================
__device__ __forceinline__ void split_bf16(float x, __nv_bfloat16& h, __nv_bfloat16& l) {
    h = __float2bfloat16_rn(x);
    l = __float2bfloat16_rn(x - __bfloat162float(h));
}

__global__ void conv_w(const float* __restrict__ W0, const float* __restrict__ W1) {
    const int idx = blockIdx.x * 256 + threadIdx.x;
    if (idx < C1 * INCH) {
        const int o = idx / INCH, k = idx % INCH;
        __nv_bfloat16 h, l;
        split_bf16(W0[idx], h, l);
        if (k < D1C) { g_W0ah[o * D1C + k] = h; g_W0al[o * D1C + k] = l; }
        else         { g_W0bh[o * D2C + k - D1C] = h; g_W0bl[o * D2C + k - D1C] = l; }
    } else {
        const int j = idx - C1 * INCH;
        if (j < C2 * C1) { __nv_bfloat16 h, l; split_bf16(W1[j], h, l); g_W1h[j] = h; g_W1l[j] = l; }
    }
}

// ===================== 3) activation transpose + split ======================
template <int DD, int NTOT>
__global__ void conv_t(const float* __restrict__ in, __nv_bfloat16* __restrict__ oh,
                       __nv_bfloat16* __restrict__ ol) {
    __shared__ float t[32][33];
    const int b = blockIdx.z;
    const int n0 = blockIdx.x * 32, d0 = blockIdx.y * 32;
    const int tx = threadIdx.x, ty = threadIdx.y;
#pragma unroll
    for (int i = 0; i < 4; i++)
        t[ty + 8 * i][tx] = in[((size_t)b * DD + d0 + ty + 8 * i) * NTOT + n0 + tx];
    __syncthreads();
#pragma unroll
    for (int i = 0; i < 4; i++) {
        const int n = n0 + ty + 8 * i;
        __nv_bfloat16 h, l;
        split_bf16(t[tx][ty + 8 * i], h, l);
        const size_t off = ((size_t)b * NTOT + n) * DD + d0 + tx;
        oh[off] = h; ol[off] = l;
    }
}

// ===================== 4) mma.sync GEMM =====================================
// out[b][m][o] = sum_k A[b][m][k] * W[o][k], bf16 3-term split fused per chunk.
// MODE 0: plain store (Zt). MODE 1: +bias +3-NN gather of Zt. MODE 2: +bias.
// CTA: 128(m) x 128(o), 8 warps as 2x4, warp tile 64x32. K-chunk 32, 2-stage.
#define TILEB 10240          // 128 rows * 80 bytes (32 bf16 + 8 pad)
#define BUFSZ (4 * TILEB)

template <int NOUT, int KIN, int MODE, int NTOT>
__global__ void __launch_bounds__(256, 2) gemm_mma(
    const __nv_bfloat16* __restrict__ Ah, const __nv_bfloat16* __restrict__ Al,
    const __nv_bfloat16* __restrict__ Bh, const __nv_bfloat16* __restrict__ Bl,
    const float* __restrict__ bias, float* __restrict__ out)
{
    constexpr int NCH = KIN / 32;
    extern __shared__ char sm[];
    const uint32_t sbase = smem_u32(sm);
    int*   sIdx = (int*)(sm + 2 * BUFSZ);
    float* sW   = (float*)(sm + 2 * BUFSZ + 1536);

    const int tid  = threadIdx.x;
    const int lane = tid & 31, wid = tid >> 5;
    const int wm = wid >> 2, wn = wid & 3;
    const int m0w = wm * 64, n0w = wn * 32;
    const int b    = blockIdx.y;
    const int mblk = blockIdx.x * 128;
    const int oblk = blockIdx.z * 128;
    const size_t bRow0 = (size_t)b * NTOT + mblk;

    if (MODE == 1 && tid < 128) {
        const int gi = (b * NPTS + mblk + tid) * 3;
#pragma unroll
        for (int t = 0; t < 3; t++) { sIdx[tid * 3 + t] = g_idx[gi + t]; sW[tid * 3 + t] = g_w[gi + t]; }
    }

    // loader coords: each thread: row tid/2, two 16B segments
    const int ldRow = tid >> 1;
    const int ldSeg = (tid & 1) * 2;

    // ldmatrix lane offsets (bytes within a tile)
    const uint32_t aOff = (uint32_t)(m0w + (lane & 15)) * 80 + (uint32_t)(lane >> 4) * 16;
    const uint32_t bOff = (uint32_t)(n0w + ((lane >> 4) << 3) + (lane & 7)) * 80 +
                          (uint32_t)((lane >> 3) & 1) * 16;

    float acc[4][4][4] = {};

    auto load_chunk = [&](int c, int buf) {
        const int koff = c * 32;
        const uint32_t dA = sbase + buf * BUFSZ + ldRow * 80 + ldSeg * 16;
        const char* sAh = (const char*)(Ah + (bRow0 + ldRow) * KIN + koff) + ldSeg * 16;
        const char* sAl = (const char*)(Al + (bRow0 + ldRow) * KIN + koff) + ldSeg * 16;
        const char* sBh = (const char*)(Bh + (size_t)(oblk + ldRow) * KIN + koff) + ldSeg * 16;
        const char* sBl = (const char*)(Bl + (size_t)(oblk + ldRow) * KIN + koff) + ldSeg * 16;
        CP16(dA,             sAh);      CP16(dA + 16,             sAh + 16);
        CP16(dA + TILEB,     sAl);      CP16(dA + TILEB + 16,     sAl + 16);
        CP16(dA + 2 * TILEB, sBh);      CP16(dA + 2 * TILEB + 16, sBh + 16);
        CP16(dA + 3 * TILEB, sBl);      CP16(dA + 3 * TILEB + 16, sBl + 16);
    };

    load_chunk(0, 0);
    CP_COMMIT();

    int buf = 0;
    for (int c = 0; c < NCH; c++) {
        if (c + 1 < NCH) { load_chunk(c + 1, buf ^ 1); CP_COMMIT(); CP_WAIT1(); }
        else             { CP_WAIT0(); }
        __syncthreads();
        const uint32_t aHb = sbase + buf * BUFSZ;
#pragma unroll
        for (int ks = 0; ks < 2; ks++) {
            const uint32_t kb = ks * 32;
            uint32_t bh[4][2], bl[4][2];
            {
                uint32_t t4[4];
                ldm4(t4, aHb + 2 * TILEB + bOff + kb);
                bh[0][0] = t4[0]; bh[0][1] = t4[1]; bh[1][0] = t4[2]; bh[1][1] = t4[3];
                ldm4(t4, aHb + 2 * TILEB + bOff + kb + 16 * 80);
                bh[2][0] = t4[0]; bh[2][1] = t4[1]; bh[3][0] = t4[2]; bh[3][1] = t4[3];
                ldm4(t4, aHb + 3 * TILEB + bOff + kb);
                bl[0][0] = t4[0]; bl[0][1] = t4[1]; bl[1][0] = t4[2]; bl[1][1] = t4[3];
                ldm4(t4, aHb + 3 * TILEB + bOff + kb + 16 * 80);
                bl[2][0] = t4[0]; bl[2][1] = t4[1]; bl[3][0] = t4[2]; bl[3][1] = t4[3];
            }
#pragma unroll
            for (int i = 0; i < 4; i++) {
                uint32_t ah[4], al[4];
                ldm4(ah, aHb + aOff + kb + i * 16 * 80);
                ldm4(al, aHb + TILEB + aOff + kb + i * 16 * 80);
#pragma unroll
                for (int j = 0; j < 4; j++) {
                    mma16816(acc[i][j], ah, bh[j]);
                    mma16816(acc[i][j], al, bh[j]);
                    mma16816(acc[i][j], ah, bl[j]);
                }
            }
        }
        __syncthreads();
        buf ^= 1;
    }

    // ------------- epilogue -------------
    float2 bias2[4];
    if (MODE >= 1) {
#pragma unroll
        for (int j = 0; j < 4; j++)
            bias2[j] = *(const float2*)&bias[oblk + n0w + 8 * j + 2 * (lane & 3)];
    }
#pragma unroll
    for (int i = 0; i < 4; i++) {
#pragma unroll
        for (int s = 0; s < 2; s++) {
            const int rl = m0w + 16 * i + 8 * s + (lane >> 2);
            float* orow = out + (bRow0 + rl) * NOUT;
            const float *z0 = nullptr, *z1 = nullptr, *z2 = nullptr;
            float w0 = 0.f, w1 = 0.f, w2 = 0.f;
            if (MODE == 1) {
                z0 = g_Zt + ((size_t)b * SPTS + sIdx[rl * 3 + 0]) * C1;
                z1 = g_Zt + ((size_t)b * SPTS + sIdx[rl * 3 + 1]) * C1;
                z2 = g_Zt + ((size_t)b * SPTS + sIdx[rl * 3 + 2]) * C1;
                w0 = sW[rl * 3 + 0]; w1 = sW[rl * 3 + 1]; w2 = sW[rl * 3 + 2];
            }
#pragma unroll
            for (int j = 0; j < 4; j++) {
                const int col = oblk + n0w + 8 * j + 2 * (lane & 3);
                float v0 = acc[i][j][2 * s], v1 = acc[i][j][2 * s + 1];
                if (MODE >= 1) { v0 += bias2[j].x; v1 += bias2[j].y; }
                if (MODE == 1) {
                    float2 za = *(const float2*)(z0 + col);
                    float2 zb = *(const float2*)(z1 + col);
                    float2 zc = *(const float2*)(z2 + col);
                    v0 += w0 * za.x + w1 * zb.x + w2 * zc.x;
                    v1 += w0 * za.y + w1 * zb.y + w2 * zc.y;
                }
                *(float2*)(orow + col - oblk * 0) = make_float2(v0, v1);
            }
        }
    }
}

// ===================== 5) BN reductions =====================================
template <int C>
__global__ void reduce_part(const float* __restrict__ Y, float* __restrict__ ps,
                            float* __restrict__ pq) {
    const int col = blockIdx.x * 32 + (threadIdx.x & 31);
    const int w = threadIdx.x >> 5;
    const int g = blockIdx.y;
    float s = 0.f, q = 0.f;
    const int r0 = g * 1024, r1 = r0 + 1024;
    for (int r = r0 + w; r < r1; r += 8) {
        float v = Y[(size_t)r * C + col];
        s += v; q = fmaf(v, v, q);
    }
    __shared__ float sh[2][8][32];
    sh[0][w][threadIdx.x & 31] = s;
    sh[1][w][threadIdx.x & 31] = q;
    __syncthreads();
    if (w == 0) {
        const int l = threadIdx.x & 31;
        float ss = 0.f, qq = 0.f;
#pragma unroll
        for (int k = 0; k < 8; k++) { ss += sh[0][k][l]; qq += sh[1][k][l]; }
        ps[col * 64 + g] = ss;
        pq[col * 64 + g] = qq;
    }
}

__global__ void reduce_fin(const float* __restrict__ ps, const float* __restrict__ pq,
                           const float* __restrict__ gam, const float* __restrict__ bet,
                           float* __restrict__ ga, float* __restrict__ gc) {
    const int c = blockIdx.x, t = threadIdx.x;
    __shared__ float ss[64], qq[64];
    ss[t] = ps[c * 64 + t]; qq[t] = pq[c * 64 + t];
    __syncthreads();
    for (int st = 32; st > 0; st >>= 1) {
        if (t < st) { ss[t] += ss[t + st]; qq[t] += qq[t + st]; }
        __syncthreads();
    }
    if (t == 0) {
        const float cnt = (float)(BB * NPTS);
        const float mean = ss[0] / cnt;
        const float var = qq[0] / cnt - mean * mean;
        const float a = gam[c] * rsqrtf(var + 1e-5f);
        ga[c] = a; gc[c] = bet[c] - mean * a;
    }
}

// ===================== 6) BN1 + relu + split -> A2 ==========================
__global__ void conv_y1() {
    const int i4 = blockIdx.x * 256 + threadIdx.x;     // float4 index
    const int o0 = (i4 & 63) * 4;
    float4 v = ((const float4*)g_Y1)[i4];
    float4 a = *(const float4*)(g_a0 + o0);
    float4 c = *(const float4*)(g_c0 + o0);
    float r0 = fmaxf(fmaf(a.x, v.x, c.x), 0.f);
    float r1 = fmaxf(fmaf(a.y, v.y, c.y), 0.f);
    float r2 = fmaxf(fmaf(a.z, v.z, c.z), 0.f);
    float r3 = fmaxf(fmaf(a.w, v.w, c.w), 0.f);
    __nv_bfloat16 h[4], l[4];
    split_bf16(r0, h[0], l[0]); split_bf16(r1, h[1], l[1]);
    split_bf16(r2, h[2], l[2]); split_bf16(r3, h[3], l[3]);
    ushort4 hv = make_ushort4(__bfloat16_as_ushort(h[0]), __bfloat16_as_ushort(h[1]),
                              __bfloat16_as_ushort(h[2]), __bfloat16_as_ushort(h[3]));
    ushort4 lv = make_ushort4(__bfloat16_as_ushort(l[0]), __bfloat16_as_ushort(l[1]),
                              __bfloat16_as_ushort(l[2]), __bfloat16_as_ushort(l[3]));
    ((ushort4*)g_A2h)[i4] = hv;
    ((ushort4*)g_A2l)[i4] = lv;
}

// ===================== 7) BN2 + relu + transpose -> out =====================
__global__ void apply2(float* __restrict__ out) {
    __shared__ float t[32][33];
    const int b = blockIdx.z;
    const int n0 = blockIdx.x * 32, o0 = blockIdx.y * 32;
    const int tx = threadIdx.x, ty = threadIdx.y;
    const float a = g_a1[o0 + tx], c = g_c1[o0 + tx];
#pragma unroll
    for (int i = 0; i < 4; i++) {
        const int n = n0 + ty + 8 * i;
        float v = g_Y2[((size_t)b * NPTS + n) * C2 + o0 + tx];
        t[tx][ty + 8 * i] = fmaxf(fmaf(a, v, c), 0.f);
    }
    __syncthreads();
#pragma unroll
    for (int i = 0; i < 4; i++) {
        const int o = o0 + ty + 8 * i;
        out[((size_t)b * C2 + o) * NPTS + n0 + tx] = t[ty + 8 * i][tx];
    }
}

// ===================== launch ===============================================
extern "C" void kernel_launch(void* const* d_in, const int* in_sizes, int n_in,
                              void* d_out, int out_size) {
    const float* xyz1    = (const float*)d_in[0];
    const float* xyz2    = (const float*)d_in[1];
    const float* points1 = (const float*)d_in[2];
    const float* points2 = (const float*)d_in[3];
    const float* W0      = (const float*)d_in[4];
    const float* b0      = (const float*)d_in[5];
    const float* g0      = (const float*)d_in[6];
    const float* be0     = (const float*)d_in[7];
    const float* W1      = (const float*)d_in[8];
    const float* b1      = (const float*)d_in[9];
    const float* g1      = (const float*)d_in[10];
    const float* be1     = (const float*)d_in[11];
    float* out = (float*)d_out;

    __nv_bfloat16 *p1h, *p1l, *p2h, *p2l, *a2h, *a2l;
    __nv_bfloat16 *w0ah, *w0al, *w0bh, *w0bl, *w1h, *w1l;
    float *zt, *y1, *y2, *p1s, *p1q, *p2s, *p2q, *a0, *c0, *a1, *c1;
    cudaGetSymbolAddress((void**)&p1h, g_P1h);  cudaGetSymbolAddress((void**)&p1l, g_P1l);
    cudaGetSymbolAddress((void**)&p2h, g_P2h);  cudaGetSymbolAddress((void**)&p2l, g_P2l);
    cudaGetSymbolAddress((void**)&a2h, g_A2h);  cudaGetSymbolAddress((void**)&a2l, g_A2l);
    cudaGetSymbolAddress((void**)&w0ah, g_W0ah); cudaGetSymbolAddress((void**)&w0al, g_W0al);
    cudaGetSymbolAddress((void**)&w0bh, g_W0bh); cudaGetSymbolAddress((void**)&w0bl, g_W0bl);
    cudaGetSymbolAddress((void**)&w1h, g_W1h);   cudaGetSymbolAddress((void**)&w1l, g_W1l);
    cudaGetSymbolAddress((void**)&zt, g_Zt);
    cudaGetSymbolAddress((void**)&y1, g_Y1);     cudaGetSymbolAddress((void**)&y2, g_Y2);
    cudaGetSymbolAddress((void**)&p1s, g_p1s);   cudaGetSymbolAddress((void**)&p1q, g_p1q);
    cudaGetSymbolAddress((void**)&p2s, g_p2s);   cudaGetSymbolAddress((void**)&p2q, g_p2q);
    cudaGetSymbolAddress((void**)&a0, g_a0);     cudaGetSymbolAddress((void**)&c0, g_c0);
    cudaGetSymbolAddress((void**)&a1, g_a1);     cudaGetSymbolAddress((void**)&c1, g_c1);

    const int SMEM = 2 * BUFSZ + 1536 + 1536;   // 84992 bytes
    cudaFuncSetAttribute(gemm_mma<256, 256, 0, SPTS>, cudaFuncAttributeMaxDynamicSharedMemorySize, SMEM);
    cudaFuncSetAttribute(gemm_mma<256, 128, 1, NPTS>, cudaFuncAttributeMaxDynamicSharedMemorySize, SMEM);
    cudaFuncSetAttribute(gemm_mma<128, 256, 2, NPTS>, cudaFuncAttributeMaxDynamicSharedMemorySize, SMEM);

    knn_kernel<<<dim3(NPTS / 256, BB), 256>>>(xyz1, xyz2);
    conv_w<<<(C1 * INCH + C2 * C1 + 255) / 256, 256>>>(W0, W1);
    conv_t<D2C, SPTS><<<dim3(SPTS / 32, D2C / 32, BB), dim3(32, 8)>>>(points2, p2h, p2l);
    conv_t<D1C, NPTS><<<dim3(NPTS / 32, D1C / 32, BB), dim3(32, 8)>>>(points1, p1h, p1l);

    gemm_mma<256, 256, 0, SPTS><<<dim3(SPTS / 128, BB, 2), 256, SMEM>>>(p2h, p2l, w0bh, w0bl, b0, zt);
    gemm_mma<256, 128, 1, NPTS><<<dim3(NPTS / 128, BB, 2), 256, SMEM>>>(p1h, p1l, w0ah, w0al, b0, y1);

    reduce_part<C1><<<dim3(C1 / 32, 64), 256>>>(y1, p1s, p1q);
    reduce_fin<<<C1, 64>>>(p1s, p1q, g0, be0, a0, c0);
    conv_y1<<<(BB * NPTS * C1 / 4) / 256, 256>>>();

    gemm_mma<128, 256, 2, NPTS><<<dim3(NPTS / 128, BB, 1), 256, SMEM>>>(a2h, a2l, w1h, w1l, b1, y2);

    reduce_part<C2><<<dim3(C2 / 32, 64), 256>>>(y2, p2s, p2q);
    reduce_fin<<<C2, 64>>>(p2s, p2q, g1, be1, a1, c1);
    apply2<<<dim3(NPTS / 32, C2 / 32, BB), dim3(32, 8)>>>(out);
}

// round 6
// speedup vs baseline: 1.6813x; 1.1387x over previous
#include <cuda_runtime.h>
#include <cuda_bf16.h>
#include <cstdint>

#define BB   8
#define NPTS 8192
#define SPTS 2048
#define D1C  128
#define D2C  256
#define INCH 384
#define C1   256
#define C2   128
#define NPART 512            // per-column BN partial slots (b*64 + mblk)

// ===================== PTX helpers (standard sm_80+ ISA only) ===============
__device__ __forceinline__ uint32_t smem_u32(const void* p) {
    uint32_t a;
    asm("{ .reg .u64 t; cvta.to.shared.u64 t, %1; cvt.u32.u64 %0, t; }" : "=r"(a) : "l"(p));
    return a;
}
#define CP16(dst, src) \
    asm volatile("cp.async.cg.shared.global [%0], [%1], 16;" :: "r"(dst), "l"(src))
#define CP_COMMIT() asm volatile("cp.async.commit_group;" ::: "memory")
#define CP_WAIT0()  asm volatile("cp.async.wait_group 0;" ::: "memory")
#define CP_WAIT1()  asm volatile("cp.async.wait_group 1;" ::: "memory")

__device__ __forceinline__ void ldm4(uint32_t* r, uint32_t addr) {
    asm volatile("ldmatrix.sync.aligned.m8n8.x4.shared.b16 {%0,%1,%2,%3}, [%4];"
                 : "=r"(r[0]), "=r"(r[1]), "=r"(r[2]), "=r"(r[3]) : "r"(addr));
}
__device__ __forceinline__ void mma16816(float* c, const uint32_t* a, const uint32_t* b) {
    asm volatile("mma.sync.aligned.m16n8k16.row.col.f32.bf16.bf16.f32 "
                 "{%0,%1,%2,%3}, {%4,%5,%6,%7}, {%8,%9}, {%0,%1,%2,%3};"
                 : "+f"(c[0]), "+f"(c[1]), "+f"(c[2]), "+f"(c[3])
                 : "r"(a[0]), "r"(a[1]), "r"(a[2]), "r"(a[3]), "r"(b[0]), "r"(b[1]));
}

// ===================== scratch ==============================================
__device__ int   g_idx[BB * NPTS * 3];
__device__ float g_w[BB * NPTS * 3];

__device__ __nv_bfloat16 g_W0ah[C1 * D1C], g_W0al[C1 * D1C];
__device__ __nv_bfloat16 g_W0bh[C1 * D2C], g_W0bl[C1 * D2C];
__device__ __nv_bfloat16 g_W1h[C2 * C1],   g_W1l[C2 * C1];
__device__ __nv_bfloat16 g_P1h[BB * NPTS * D1C], g_P1l[BB * NPTS * D1C];
__device__ __nv_bfloat16 g_P2h[BB * SPTS * D2C], g_P2l[BB * SPTS * D2C];

__device__ float g_Zt[BB * SPTS * C1];     // [b][s][o]
__device__ float g_Y1[BB * NPTS * C1];     // [b][n][o]
__device__ float g_Y2[BB * NPTS * C2];     // [b][n][o]
__device__ float g_p1s[C1 * NPART], g_p1q[C1 * NPART];
__device__ float g_p2s[C2 * NPART], g_p2q[C2 * NPART];
__device__ float g_a0[C1], g_c0[C1], g_a1[C2], g_c1[C2];

// ===================== 1) 3-NN =============================================
__global__ void knn_kernel(const float* __restrict__ xyz1,
                           const float* __restrict__ xyz2) {
    __shared__ float4 s2[SPTS];
    const int b = blockIdx.y;
    const int tid = threadIdx.x;
    for (int s = tid; s < SPTS; s += 256) {
        float x = xyz2[(b * 3 + 0) * SPTS + s];
        float y = xyz2[(b * 3 + 1) * SPTS + s];
        float z = xyz2[(b * 3 + 2) * SPTS + s];
        s2[s] = make_float4(x, y, z, x * x + y * y + z * z);
    }
    __syncthreads();
    const int n = blockIdx.x * 256 + tid;
    const float px = xyz1[(b * 3 + 0) * NPTS + n];
    const float py = xyz1[(b * 3 + 1) * NPTS + n];
    const float pz = xyz1[(b * 3 + 2) * NPTS + n];
    const float n1 = px * px + py * py + pz * pz;
    float d0 = 3.4e38f, d1 = 3.4e38f, d2 = 3.4e38f;
    int   i0 = 0, i1 = 0, i2 = 0;
#pragma unroll 4
    for (int s = 0; s < SPTS; s++) {
        float4 q = s2[s];
        float d = n1 + q.w - 2.f * (px * q.x + py * q.y + pz * q.z);
        if (d < d2) {
            if (d < d1) {
                d2 = d1; i2 = i1;
                if (d < d0) { d1 = d0; i1 = i0; d0 = d; i0 = s; }
                else        { d1 = d;  i1 = s; }
            } else { d2 = d; i2 = s; }
        }
    }
    const float r0 = 1.f / (d0 + 1e-8f);
    const float r1 = 1.f / (d1 + 1e-8f);
    const float r2 = 1.f / (d2 + 1e-8f);
    const float inv = 1.f / (r0 + r1 + r2);
    const int base = (b * NPTS + n) * 3;
    g_idx[base + 0] = i0; g_idx[base + 1] = i1; g_idx[base + 2] = i2;
    g_w[base + 0] = r0 * inv; g_w[base + 1] = r1 * inv; g_w[base + 2] = r2 * inv;
}

// ===================== 2) weight split ======================================
__device__ __forceinline__ void split_bf16(float x, __nv_bfloat16& h, __nv_bfloat16& l) {
    h = __float2bfloat16_rn(x);
    l = __float2bfloat16_rn(x - __bfloat162float(h));
}

__global__ void conv_w(const float* __restrict__ W0, const float* __restrict__ W1) {
    const int idx = blockIdx.x * 256 + threadIdx.x;
    if (idx < C1 * INCH) {
        const int o = idx / INCH, k = idx % INCH;
        __nv_bfloat16 h, l;
        split_bf16(W0[idx], h, l);
        if (k < D1C) { g_W0ah[o * D1C + k] = h; g_W0al[o * D1C + k] = l; }
        else         { g_W0bh[o * D2C + k - D1C] = h; g_W0bl[o * D2C + k - D1C] = l; }
    } else {
        const int j = idx - C1 * INCH;
        if (j < C2 * C1) { __nv_bfloat16 h, l; split_bf16(W1[j], h, l); g_W1h[j] = h; g_W1l[j] = l; }
    }
}

// ===================== 3) activation transpose + split ======================
template <int DD, int NTOT>
__global__ void conv_t(const float* __restrict__ in, __nv_bfloat16* __restrict__ oh,
                       __nv_bfloat16* __restrict__ ol) {
    __shared__ float t[32][33];
    const int b = blockIdx.z;
    const int n0 = blockIdx.x * 32, d0 = blockIdx.y * 32;
    const int tx = threadIdx.x, ty = threadIdx.y;
#pragma unroll
    for (int i = 0; i < 4; i++)
        t[ty + 8 * i][tx] = in[((size_t)b * DD + d0 + ty + 8 * i) * NTOT + n0 + tx];
    __syncthreads();
#pragma unroll
    for (int i = 0; i < 4; i++) {
        const int n = n0 + ty + 8 * i;
        __nv_bfloat16 h, l;
        split_bf16(t[tx][ty + 8 * i], h, l);
        const size_t off = ((size_t)b * NTOT + n) * DD + d0 + tx;
        oh[off] = h; ol[off] = l;
    }
}

// ===================== shared epilogue partial helpers ======================
// warp layout: wm(2) x wn(4); warp tile 64(m) x 32(o)
#define TILEB 10240          // 128 rows * 80 bytes (32 bf16 + 8 pad)
#define BUFSZ (4 * TILEB)

// ===================== 4a) mma.sync GEMM (bf16 pre-split A) =================
// MODE 0: plain store (Zt). MODE 1: +bias +3-NN gather of Zt, +BN partials.
template <int NOUT, int KIN, int MODE, int NTOT>
__global__ void __launch_bounds__(256, 2) gemm_mma(
    const __nv_bfloat16* __restrict__ Ah, const __nv_bfloat16* __restrict__ Al,
    const __nv_bfloat16* __restrict__ Bh, const __nv_bfloat16* __restrict__ Bl,
    const float* __restrict__ bias, float* __restrict__ out,
    float* __restrict__ ps, float* __restrict__ pq)
{
    constexpr int NCH = KIN / 32;
    extern __shared__ char sm[];
    const uint32_t sbase = smem_u32(sm);
    int*   sIdx = (int*)(sm + 2 * BUFSZ);
    float* sW   = (float*)(sm + 2 * BUFSZ + 1536);
    float* sPs  = (float*)(sm + 2 * BUFSZ + 3072);    // [2][128]
    float* sPq  = sPs + 256;

    const int tid  = threadIdx.x;
    const int lane = tid & 31, wid = tid >> 5;
    const int wm = wid >> 2, wn = wid & 3;
    const int m0w = wm * 64, n0w = wn * 32;
    const int b    = blockIdx.y;
    const int mblk = blockIdx.x * 128;
    const int oblk = blockIdx.z * 128;
    const size_t bRow0 = (size_t)b * NTOT + mblk;

    if (MODE == 1 && tid < 128) {
        const int gi = (b * NPTS + mblk + tid) * 3;
#pragma unroll
        for (int t = 0; t < 3; t++) { sIdx[tid * 3 + t] = g_idx[gi + t]; sW[tid * 3 + t] = g_w[gi + t]; }
    }

    const int ldRow = tid >> 1;
    const int ldSeg = (tid & 1) * 2;

    const uint32_t aOff = (uint32_t)(m0w + (lane & 15)) * 80 + (uint32_t)(lane >> 4) * 16;
    const uint32_t bOff = (uint32_t)(n0w + ((lane >> 4) << 3) + (lane & 7)) * 80 +
                          (uint32_t)((lane >> 3) & 1) * 16;

    float acc[4][4][4] = {};

    auto load_chunk = [&](int c, int buf) {
        const int koff = c * 32;
        const uint32_t dA = sbase + buf * BUFSZ + ldRow * 80 + ldSeg * 16;
        const char* sAh = (const char*)(Ah + (bRow0 + ldRow) * KIN + koff) + ldSeg * 16;
        const char* sAl = (const char*)(Al + (bRow0 + ldRow) * KIN + koff) + ldSeg * 16;
        const char* sBh = (const char*)(Bh + (size_t)(oblk + ldRow) * KIN + koff) + ldSeg * 16;
        const char* sBl = (const char*)(Bl + (size_t)(oblk + ldRow) * KIN + koff) + ldSeg * 16;
        CP16(dA,             sAh);      CP16(dA + 16,             sAh + 16);
        CP16(dA + TILEB,     sAl);      CP16(dA + TILEB + 16,     sAl + 16);
        CP16(dA + 2 * TILEB, sBh);      CP16(dA + 2 * TILEB + 16, sBh + 16);
        CP16(dA + 3 * TILEB, sBl);      CP16(dA + 3 * TILEB + 16, sBl + 16);
    };

    load_chunk(0, 0);
    CP_COMMIT();

    int buf = 0;
    for (int c = 0; c < NCH; c++) {
        if (c + 1 < NCH) { load_chunk(c + 1, buf ^ 1); CP_COMMIT(); CP_WAIT1(); }
        else             { CP_WAIT0(); }
        __syncthreads();
        const uint32_t aHb = sbase + buf * BUFSZ;
#pragma unroll
        for (int ks = 0; ks < 2; ks++) {
            const uint32_t kb = ks * 32;
            uint32_t bh[4][2], bl[4][2];
            {
                uint32_t t4[4];
                ldm4(t4, aHb + 2 * TILEB + bOff + kb);
                bh[0][0] = t4[0]; bh[0][1] = t4[1]; bh[1][0] = t4[2]; bh[1][1] = t4[3];
                ldm4(t4, aHb + 2 * TILEB + bOff + kb + 16 * 80);
                bh[2][0] = t4[0]; bh[2][1] = t4[1]; bh[3][0] = t4[2]; bh[3][1] = t4[3];
                ldm4(t4, aHb + 3 * TILEB + bOff + kb);
                bl[0][0] = t4[0]; bl[0][1] = t4[1]; bl[1][0] = t4[2]; bl[1][1] = t4[3];
                ldm4(t4, aHb + 3 * TILEB + bOff + kb + 16 * 80);
                bl[2][0] = t4[0]; bl[2][1] = t4[1]; bl[3][0] = t4[2]; bl[3][1] = t4[3];
            }
#pragma unroll
            for (int i = 0; i < 4; i++) {
                uint32_t ah[4], al[4];
                ldm4(ah, aHb + aOff + kb + i * 16 * 80);
                ldm4(al, aHb + TILEB + aOff + kb + i * 16 * 80);
#pragma unroll
                for (int j = 0; j < 4; j++) {
                    mma16816(acc[i][j], ah, bh[j]);
                    mma16816(acc[i][j], al, bh[j]);
                    mma16816(acc[i][j], ah, bl[j]);
                }
            }
        }
        __syncthreads();
        buf ^= 1;
    }

    // ------------- epilogue -------------
    float2 bias2[4];
    if (MODE >= 1) {
#pragma unroll
        for (int j = 0; j < 4; j++)
            bias2[j] = *(const float2*)&bias[oblk + n0w + 8 * j + 2 * (lane & 3)];
    }
    float sc[8] = {}, qc[8] = {};
#pragma unroll
    for (int i = 0; i < 4; i++) {
#pragma unroll
        for (int s = 0; s < 2; s++) {
            const int rl = m0w + 16 * i + 8 * s + (lane >> 2);
            float* orow = out + (bRow0 + rl) * NOUT;
            const float *z0 = nullptr, *z1 = nullptr, *z2 = nullptr;
            float w0 = 0.f, w1 = 0.f, w2 = 0.f;
            if (MODE == 1) {
                z0 = g_Zt + ((size_t)b * SPTS + sIdx[rl * 3 + 0]) * C1;
                z1 = g_Zt + ((size_t)b * SPTS + sIdx[rl * 3 + 1]) * C1;
                z2 = g_Zt + ((size_t)b * SPTS + sIdx[rl * 3 + 2]) * C1;
                w0 = sW[rl * 3 + 0]; w1 = sW[rl * 3 + 1]; w2 = sW[rl * 3 + 2];
            }
#pragma unroll
            for (int j = 0; j < 4; j++) {
                const int col = oblk + n0w + 8 * j + 2 * (lane & 3);
                float v0 = acc[i][j][2 * s], v1 = acc[i][j][2 * s + 1];
                if (MODE >= 1) { v0 += bias2[j].x; v1 += bias2[j].y; }
                if (MODE == 1) {
                    float2 za = *(const float2*)(z0 + col);
                    float2 zb = *(const float2*)(z1 + col);
                    float2 zc = *(const float2*)(z2 + col);
                    v0 += w0 * za.x + w1 * zb.x + w2 * zc.x;
                    v1 += w0 * za.y + w1 * zb.y + w2 * zc.y;
                }
                if (MODE == 1) {
                    sc[2 * j] += v0;     qc[2 * j] = fmaf(v0, v0, qc[2 * j]);
                    sc[2 * j + 1] += v1; qc[2 * j + 1] = fmaf(v1, v1, qc[2 * j + 1]);
                }
                *(float2*)(orow + col) = make_float2(v0, v1);
            }
        }
    }
    if (MODE == 1) {
#pragma unroll
        for (int k = 0; k < 8; k++) {
#pragma unroll
            for (int off = 16; off >= 4; off >>= 1) {
                sc[k] += __shfl_down_sync(0xffffffffu, sc[k], off);
                qc[k] += __shfl_down_sync(0xffffffffu, qc[k], off);
            }
        }
        if (lane < 4) {
#pragma unroll
            for (int j = 0; j < 4; j++) {
                const int cl = n0w + 8 * j + 2 * lane;
                sPs[wm * 128 + cl] = sc[2 * j];     sPq[wm * 128 + cl] = qc[2 * j];
                sPs[wm * 128 + cl + 1] = sc[2 * j + 1]; sPq[wm * 128 + cl + 1] = qc[2 * j + 1];
            }
        }
        __syncthreads();
        if (tid < 128) {
            const float S = sPs[tid] + sPs[128 + tid];
            const float Q = sPq[tid] + sPq[128 + tid];
            const int slot = (oblk + tid) * NPART + b * 64 + blockIdx.x;
            ps[slot] = S; pq[slot] = Q;
        }
    }
}

// ===================== 4b) layer-2 GEMM: fp32 Y1 staging + BN + relu ========
__global__ void __launch_bounds__(256, 2) gemm_y2(
    const float* __restrict__ Y1, const __nv_bfloat16* __restrict__ Bh,
    const __nv_bfloat16* __restrict__ Bl, const float* __restrict__ bias,
    float* __restrict__ out, float* __restrict__ ps, float* __restrict__ pq)
{
    constexpr int NCH = C1 / 32;       // 8
    extern __shared__ char sm[];
    const uint32_t sbase = smem_u32(sm);
    float* sA0 = (float*)(sm + 2 * BUFSZ);            // [256]
    float* sC0 = sA0 + 256;
    float* sPs = sC0 + 256;                           // [2][128]
    float* sPq = sPs + 256;

    const int tid  = threadIdx.x;
    const int lane = tid & 31, wid = tid >> 5;
    const int wm = wid >> 2, wn = wid & 3;
    const int m0w = wm * 64, n0w = wn * 32;
    const int b    = blockIdx.y;
    const int mblk = blockIdx.x * 128;
    const size_t bRow0 = (size_t)b * NPTS + mblk;

    sA0[tid] = g_a0[tid];
    sC0[tid] = g_c0[tid];

    const int ldRow = tid >> 1;
    const int ldSeg = (tid & 1) * 2;         // for B cp.async (2x16B)
    const int aCol0 = (tid & 1) * 16;        // 16 fp32 per thread for A

    const uint32_t aOff = (uint32_t)(m0w + (lane & 15)) * 80 + (uint32_t)(lane >> 4) * 16;
    const uint32_t bOff = (uint32_t)(n0w + ((lane >> 4) << 3) + (lane & 7)) * 80 +
                          (uint32_t)((lane >> 3) & 1) * 16;

    float acc[4][4][4] = {};
    float4 rA[4];

    auto ldgA = [&](int c) {
        const float* src = Y1 + (bRow0 + ldRow) * C1 + c * 32 + aCol0;
#pragma unroll
        for (int i = 0; i < 4; i++) rA[i] = __ldg((const float4*)(src + 4 * i));
    };
    auto cpB = [&](int c, int bf) {
        const int koff = c * 32;
        const uint32_t dB = sbase + bf * BUFSZ + 2 * TILEB + ldRow * 80 + ldSeg * 16;
        const char* sBh = (const char*)(Bh + (size_t)ldRow * C1 + koff) + ldSeg * 16;
        const char* sBl = (const char*)(Bl + (size_t)ldRow * C1 + koff) + ldSeg * 16;
        CP16(dB,          sBh); CP16(dB + 16,          sBh + 16);
        CP16(dB + TILEB,  sBl); CP16(dB + TILEB + 16,  sBl + 16);
    };
    auto stsA = [&](int c, int bf) {
        const int colBase = c * 32 + aCol0;
        uint32_t hw[8], lw[8];
#pragma unroll
        for (int q = 0; q < 4; q++) {
            const float4 v = rA[q];
            const float4 a = *(const float4*)(sA0 + colBase + 4 * q);
            const float4 cc = *(const float4*)(sC0 + colBase + 4 * q);
            float r0 = fmaxf(fmaf(a.x, v.x, cc.x), 0.f);
            float r1 = fmaxf(fmaf(a.y, v.y, cc.y), 0.f);
            float r2 = fmaxf(fmaf(a.z, v.z, cc.z), 0.f);
            float r3 = fmaxf(fmaf(a.w, v.w, cc.w), 0.f);
            __nv_bfloat16 h0, l0, h1, l1, h2, l2, h3, l3;
            split_bf16(r0, h0, l0); split_bf16(r1, h1, l1);
            split_bf16(r2, h2, l2); split_bf16(r3, h3, l3);
            hw[2 * q]     = (uint32_t)__bfloat16_as_ushort(h0) | ((uint32_t)__bfloat16_as_ushort(h1) << 16);
            hw[2 * q + 1] = (uint32_t)__bfloat16_as_ushort(h2) | ((uint32_t)__bfloat16_as_ushort(h3) << 16);
            lw[2 * q]     = (uint32_t)__bfloat16_as_ushort(l0) | ((uint32_t)__bfloat16_as_ushort(l1) << 16);
            lw[2 * q + 1] = (uint32_t)__bfloat16_as_ushort(l2) | ((uint32_t)__bfloat16_as_ushort(l3) << 16);
        }
        uint32_t* dH = (uint32_t*)(sm + bf * BUFSZ + ldRow * 80 + (tid & 1) * 32);
        uint32_t* dL = (uint32_t*)(sm + bf * BUFSZ + TILEB + ldRow * 80 + (tid & 1) * 32);
#pragma unroll
        for (int q = 0; q < 8; q++) { dH[q] = hw[q]; dL[q] = lw[q]; }
    };

    ldgA(0);
    cpB(0, 0);
    CP_COMMIT();
    __syncthreads();   // sA0/sC0 ready

    int buf = 0;
    for (int c = 0; c < NCH; c++) {
        stsA(c, buf);
        if (c + 1 < NCH) { cpB(c + 1, buf ^ 1); CP_COMMIT(); ldgA(c + 1); CP_WAIT1(); }
        else             { CP_WAIT0(); }
        __syncthreads();
        const uint32_t aHb = sbase + buf * BUFSZ;
#pragma unroll
        for (int ks = 0; ks < 2; ks++) {
            const uint32_t kb = ks * 32;
            uint32_t bh[4][2], bl[4][2];
            {
                uint32_t t4[4];
                ldm4(t4, aHb + 2 * TILEB + bOff + kb);
                bh[0][0] = t4[0]; bh[0][1] = t4[1]; bh[1][0] = t4[2]; bh[1][1] = t4[3];
                ldm4(t4, aHb + 2 * TILEB + bOff + kb + 16 * 80);
                bh[2][0] = t4[0]; bh[2][1] = t4[1]; bh[3][0] = t4[2]; bh[3][1] = t4[3];
                ldm4(t4, aHb + 3 * TILEB + bOff + kb);
                bl[0][0] = t4[0]; bl[0][1] = t4[1]; bl[1][0] = t4[2]; bl[1][1] = t4[3];
                ldm4(t4, aHb + 3 * TILEB + bOff + kb + 16 * 80);
                bl[2][0] = t4[0]; bl[2][1] = t4[1]; bl[3][0] = t4[2]; bl[3][1] = t4[3];
            }
#pragma unroll
            for (int i = 0; i < 4; i++) {
                uint32_t ah[4], al[4];
                ldm4(ah, aHb + aOff + kb + i * 16 * 80);
                ldm4(al, aHb + TILEB + aOff + kb + i * 16 * 80);
#pragma unroll
                for (int j = 0; j < 4; j++) {
                    mma16816(acc[i][j], ah, bh[j]);
                    mma16816(acc[i][j], al, bh[j]);
                    mma16816(acc[i][j], ah, bl[j]);
                }
            }
        }
        __syncthreads();
        buf ^= 1;
    }

    // ------------- epilogue: bias + Y2 store + BN2 partials -------------
    float2 bias2[4];
#pragma unroll
    for (int j = 0; j < 4; j++)
        bias2[j] = *(const float2*)&bias[n0w + 8 * j + 2 * (lane & 3)];
    float sc[8] = {}, qc[8] = {};
#pragma unroll
    for (int i = 0; i < 4; i++) {
#pragma unroll
        for (int s = 0; s < 2; s++) {
            const int rl = m0w + 16 * i + 8 * s + (lane >> 2);
            float* orow = out + (bRow0 + rl) * C2;
#pragma unroll
            for (int j = 0; j < 4; j++) {
                const int col = n0w + 8 * j + 2 * (lane & 3);
                float v0 = acc[i][j][2 * s] + bias2[j].x;
                float v1 = acc[i][j][2 * s + 1] + bias2[j].y;
                sc[2 * j] += v0;     qc[2 * j] = fmaf(v0, v0, qc[2 * j]);
                sc[2 * j + 1] += v1; qc[2 * j + 1] = fmaf(v1, v1, qc[2 * j + 1]);
                *(float2*)(orow + col) = make_float2(v0, v1);
            }
        }
    }
#pragma unroll
    for (int k = 0; k < 8; k++) {
#pragma unroll
        for (int off = 16; off >= 4; off >>= 1) {
            sc[k] += __shfl_down_sync(0xffffffffu, sc[k], off);
            qc[k] += __shfl_down_sync(0xffffffffu, qc[k], off);
        }
    }
    if (lane < 4) {
#pragma unroll
        for (int j = 0; j < 4; j++) {
            const int cl = n0w + 8 * j + 2 * lane;
            sPs[wm * 128 + cl] = sc[2 * j];         sPq[wm * 128 + cl] = qc[2 * j];
            sPs[wm * 128 + cl + 1] = sc[2 * j + 1]; sPq[wm * 128 + cl + 1] = qc[2 * j + 1];
        }
    }
    __syncthreads();
    if (tid < 128) {
        const float S = sPs[tid] + sPs[128 + tid];
        const float Q = sPq[tid] + sPq[128 + tid];
        const int slot = tid * NPART + b * 64 + blockIdx.x;
        ps[slot] = S; pq[slot] = Q;
    }
}

// ===================== 5) BN finalize from partials =========================
__global__ void reduce_fin(const float* __restrict__ ps, const float* __restrict__ pq,
                           const float* __restrict__ gam, const float* __restrict__ bet,
                           float* __restrict__ ga, float* __restrict__ gc) {
    const int c = blockIdx.x, t = threadIdx.x;
    float s = ps[c * NPART + t] + ps[c * NPART + t + 256];
    float q = pq[c * NPART + t] + pq[c * NPART + t + 256];
    __shared__ float ss[256], qq[256];
    ss[t] = s; qq[t] = q;
    __syncthreads();
    for (int st = 128; st > 0; st >>= 1) {
        if (t < st) { ss[t] += ss[t + st]; qq[t] += qq[t + st]; }
        __syncthreads();
    }
    if (t == 0) {
        const float cnt = (float)(BB * NPTS);
        const float mean = ss[0] / cnt;
        const float var = qq[0] / cnt - mean * mean;
        const float a = gam[c] * rsqrtf(var + 1e-5f);
        ga[c] = a; gc[c] = bet[c] - mean * a;
    }
}

// ===================== 7) BN2 + relu + transpose -> out =====================
__global__ void apply2(float* __restrict__ out) {
    __shared__ float t[32][33];
    const int b = blockIdx.z;
    const int n0 = blockIdx.x * 32, o0 = blockIdx.y * 32;
    const int tx = threadIdx.x, ty = threadIdx.y;
    const float a = g_a1[o0 + tx], c = g_c1[o0 + tx];
#pragma unroll
    for (int i = 0; i < 4; i++) {
        const int n = n0 + ty + 8 * i;
        float v = g_Y2[((size_t)b * NPTS + n) * C2 + o0 + tx];
        t[tx][ty + 8 * i] = fmaxf(fmaf(a, v, c), 0.f);
    }
    __syncthreads();
#pragma unroll
    for (int i = 0; i < 4; i++) {
        const int o = o0 + ty + 8 * i;
        out[((size_t)b * C2 + o) * NPTS + n0 + tx] = t[ty + 8 * i][tx];
    }
}

// ===================== launch ===============================================
extern "C" void kernel_launch(void* const* d_in, const int* in_sizes, int n_in,
                              void* d_out, int out_size) {
    const float* xyz1    = (const float*)d_in[0];
    const float* xyz2    = (const float*)d_in[1];
    const float* points1 = (const float*)d_in[2];
    const float* points2 = (const float*)d_in[3];
    const float* W0      = (const float*)d_in[4];
    const float* b0      = (const float*)d_in[5];
    const float* g0      = (const float*)d_in[6];
    const float* be0     = (const float*)d_in[7];
    const float* W1      = (const float*)d_in[8];
    const float* b1      = (const float*)d_in[9];
    const float* g1      = (const float*)d_in[10];
    const float* be1     = (const float*)d_in[11];
    float* out = (float*)d_out;

    __nv_bfloat16 *p1h, *p1l, *p2h, *p2l;
    __nv_bfloat16 *w0ah, *w0al, *w0bh, *w0bl, *w1h, *w1l;
    float *zt, *y1, *y2, *p1s, *p1q, *p2s, *p2q, *a0, *c0, *a1, *c1;
    cudaGetSymbolAddress((void**)&p1h, g_P1h);  cudaGetSymbolAddress((void**)&p1l, g_P1l);
    cudaGetSymbolAddress((void**)&p2h, g_P2h);  cudaGetSymbolAddress((void**)&p2l, g_P2l);
    cudaGetSymbolAddress((void**)&w0ah, g_W0ah); cudaGetSymbolAddress((void**)&w0al, g_W0al);
    cudaGetSymbolAddress((void**)&w0bh, g_W0bh); cudaGetSymbolAddress((void**)&w0bl, g_W0bl);
    cudaGetSymbolAddress((void**)&w1h, g_W1h);   cudaGetSymbolAddress((void**)&w1l, g_W1l);
    cudaGetSymbolAddress((void**)&zt, g_Zt);
    cudaGetSymbolAddress((void**)&y1, g_Y1);     cudaGetSymbolAddress((void**)&y2, g_Y2);
    cudaGetSymbolAddress((void**)&p1s, g_p1s);   cudaGetSymbolAddress((void**)&p1q, g_p1q);
    cudaGetSymbolAddress((void**)&p2s, g_p2s);   cudaGetSymbolAddress((void**)&p2q, g_p2q);
    cudaGetSymbolAddress((void**)&a0, g_a0);     cudaGetSymbolAddress((void**)&c0, g_c0);
    cudaGetSymbolAddress((void**)&a1, g_a1);     cudaGetSymbolAddress((void**)&c1, g_c1);

    const int SMEM = 2 * BUFSZ + 1536 + 1536 + 2048;    // 87040
    cudaFuncSetAttribute(gemm_mma<256, 256, 0, SPTS>, cudaFuncAttributeMaxDynamicSharedMemorySize, SMEM);
    cudaFuncSetAttribute(gemm_mma<256, 128, 1, NPTS>, cudaFuncAttributeMaxDynamicSharedMemorySize, SMEM);
    cudaFuncSetAttribute(gemm_y2, cudaFuncAttributeMaxDynamicSharedMemorySize, SMEM);

    knn_kernel<<<dim3(NPTS / 256, BB), 256>>>(xyz1, xyz2);
    conv_w<<<(C1 * INCH + C2 * C1 + 255) / 256, 256>>>(W0, W1);
    conv_t<D2C, SPTS><<<dim3(SPTS / 32, D2C / 32, BB), dim3(32, 8)>>>(points2, p2h, p2l);
    conv_t<D1C, NPTS><<<dim3(NPTS / 32, D1C / 32, BB), dim3(32, 8)>>>(points1, p1h, p1l);

    gemm_mma<256, 256, 0, SPTS><<<dim3(SPTS / 128, BB, 2), 256, SMEM>>>(p2h, p2l, w0bh, w0bl, b0, zt, nullptr, nullptr);
    gemm_mma<256, 128, 1, NPTS><<<dim3(NPTS / 128, BB, 2), 256, SMEM>>>(p1h, p1l, w0ah, w0al, b0, y1, p1s, p1q);

    reduce_fin<<<C1, 256>>>(p1s, p1q, g0, be0, a0, c0);

    gemm_y2<<<dim3(NPTS / 128, BB, 1), 256, SMEM>>>(y1, w1h, w1l, b1, y2, p2s, p2q);

    reduce_fin<<<C2, 256>>>(p2s, p2q, g1, be1, a1, c1);
    apply2<<<dim3(NPTS / 32, C2 / 32, BB), dim3(32, 8)>>>(out);
}